// round 3
// baseline (speedup 1.0000x reference)
#include <cuda_runtime.h>
#include <cstdint>

// Problem dims
#define B_ 32
#define P_ 12
#define N_ 512
#define F_ 64
#define D_ 256
#define Q_ 12
#define DT_ 0.1f

static const int BQN = B_ * Q_ * N_;  // 196608

// ---------------- scratch (device globals; no runtime alloc) ----------------
__device__ float g_tmp[(size_t)B_ * Q_ * N_ * F_];   // mixed inputs  (B,Q,N,F)
__device__ float g_h  [(size_t)B_ * Q_ * N_ * D_];   // hidden        (B,Q,N,D)
__device__ float g_q  [(size_t)B_ * Q_ * N_ * D_];
__device__ float g_k  [(size_t)B_ * Q_ * N_ * D_];
__device__ float g_v  [(size_t)B_ * Q_ * N_ * D_];
__device__ float g_S  [(size_t)B_ * Q_ * N_ * N_];   // scores/attn   (B,Q,N,N)
__device__ float g_CP [(size_t)2 * N_ * N_];         // [DT*A ; C2]  (1024x512)

// ---------------- helpers ----------------------------------------------------
__device__ __forceinline__ uint32_t f2tf32(float f) {
    uint32_t u;
    asm("cvt.rna.tf32.f32 %0, %1;" : "=r"(u) : "f"(f));
    return u;
}

__device__ __forceinline__ void mma_tf32(float* c, const uint32_t* a, const uint32_t* b) {
    asm volatile(
        "mma.sync.aligned.m16n8k8.row.col.f32.tf32.tf32.f32 "
        "{%0,%1,%2,%3}, {%4,%5,%6,%7}, {%8,%9}, {%0,%1,%2,%3};"
        : "+f"(c[0]), "+f"(c[1]), "+f"(c[2]), "+f"(c[3])
        : "r"(a[0]), "r"(a[1]), "r"(a[2]), "r"(a[3]),
          "r"(b[0]), "r"(b[1]));
}

// ---------------- K1: tmp[b,q,n,f] = sum_p inputs[b,p,n,f] * T_mix[p,q] -----
__global__ __launch_bounds__(256) void mix_kernel(const float* __restrict__ in,
                                                  const float* __restrict__ T) {
    __shared__ float Ts[P_][Q_];
    int t = threadIdx.x;
    if (t < P_ * Q_) Ts[t / Q_][t % Q_] = T[t];
    __syncthreads();
    long idx = (long)blockIdx.x * blockDim.x + t;          // over B*N*F
    if (idx >= (long)B_ * N_ * F_) return;
    int f = (int)(idx % F_);
    int n = (int)((idx / F_) % N_);
    int b = (int)(idx / ((long)F_ * N_));
    float vals[P_];
    const float* ip = in + ((long)b * P_ * N_ + n) * F_ + f;
#pragma unroll
    for (int p = 0; p < P_; p++) vals[p] = ip[(long)p * N_ * F_];
    float* op = g_tmp + ((long)b * Q_ * N_ + n) * F_ + f;
#pragma unroll
    for (int q = 0; q < Q_; q++) {
        float s = 0.f;
#pragma unroll
        for (int p = 0; p < P_; p++) s += vals[p] * Ts[p][q];
        op[(long)q * N_ * F_] = s;
    }
}

// ---------------- scale: CP[0] = DT * A --------------------------------------
__global__ __launch_bounds__(256) void scaleA_kernel(const float* __restrict__ A) {
    int i = blockIdx.x * blockDim.x + threadIdx.x;
    if (i < N_ * N_) g_CP[i] = DT_ * A[i];
}

// ---------------- tf32 tensor-core GEMM, fragment-native smem ----------------
// C = alpha * A * op(B) + beta * R (if RESID).  A: MxK row-major fp32.
// NN: B is KxN row-major.  NT: B is NxK row-major (C = A*B^T).
// Batched via blockIdx.z. RMOD>0: R row index is (row % RMOD).
// Warp tile = (BM/WM) x (BN/WN); requires BM/WM==64, (BN/WN)%8==0, K%16==0.
template <int BM, int BN, int WM, int WN, bool TRANS_B, bool RESID, int RMOD>
__global__ __launch_bounds__(WM* WN * 32) void gemm_tc(
    const float* __restrict__ A, const float* __restrict__ Bm,
    float* __restrict__ C, const float* __restrict__ R,
    int M, int Nn, int K, long sA, long sB, long sC, long sR,
    float alpha, float beta) {
    constexpr int BK = 16;
    constexpr int NT = WM * WN * 32;
    constexpr int WTM = BM / WM;           // 64
    constexpr int WTN = BN / WN;           // 64 or 32
    constexpr int FM = WTM / 16;           // 4
    constexpr int FN = WTN / 8;            // 8 or 4
    constexpr int MT = BM / 16;            // m-tiles in block
    constexpr int NTL = BN / 8;            // n-tiles in block
    constexpr int NA4 = BM * BK / (4 * NT);
    constexpr int NB4 = BN * BK / (4 * NT);

    // fragment-native layouts: one LDS.128 / LDS.64 per fragment, conflict-free
    __shared__ uint32_t Asf[2][MT][2][32][4];
    __shared__ uint32_t Bsf[2][NTL][2][32][2];

    const int bz = blockIdx.z;
    A += (long)bz * sA;
    Bm += (long)bz * sB;
    C += (long)bz * sC;
    if (RESID) R += (long)bz * sR;

    const int row0 = blockIdx.y * BM, col0 = blockIdx.x * BN;
    const int tid = threadIdx.x;
    const int lane = tid & 31, wid = tid >> 5;
    const int grp = lane >> 2, qid = lane & 3;
    const int wm = wid / WN, wn = wid % WN;

    float acc[FM][FN][4] = {};
    float4 pa[NA4], pb[NB4];

    auto g_load = [&](int k0) {
#pragma unroll
        for (int l = 0; l < NA4; l++) {
            int i = tid + l * NT;
            int r = i >> 2, kq = i & 3;
            pa[l] = *(const float4*)(A + (long)(row0 + r) * K + k0 + kq * 4);
        }
#pragma unroll
        for (int l = 0; l < NB4; l++) {
            int i = tid + l * NT;
            if (!TRANS_B) {
                int kk = i / (BN / 4), nq = i % (BN / 4);
                pb[l] = *(const float4*)(Bm + (long)(k0 + kk) * Nn + col0 + nq * 4);
            } else {
                int n = i >> 2, kq = i & 3;
                pb[l] = *(const float4*)(Bm + (long)(col0 + n) * K + k0 + kq * 4);
            }
        }
    };

    auto s_store = [&](int st) {
#pragma unroll
        for (int l = 0; l < NA4; l++) {
            int i = tid + l * NT;
            int r = i >> 2, kq = i & 3;
            int mt = r >> 4, row = r & 15;
            int kc = kq >> 1;
            int reg = ((row >> 3) & 1) | ((kq & 1) << 1);
            int lane0 = (row & 7) * 4;
            uint32_t* p = &Asf[st][mt][kc][lane0][reg];
            p[0]  = f2tf32(pa[l].x);
            p[4]  = f2tf32(pa[l].y);
            p[8]  = f2tf32(pa[l].z);
            p[12] = f2tf32(pa[l].w);
        }
#pragma unroll
        for (int l = 0; l < NB4; l++) {
            int i = tid + l * NT;
            if (!TRANS_B) {
                int kk = i / (BN / 4), nq = i % (BN / 4);     // k-row, n-quad
                int kc = kk >> 3, krem = kk & 7;
                int reg = krem >> 2;
                int nt = (nq * 4) >> 3;
                int lane0 = ((nq & 1) * 4) * 4 + (krem & 3);
                uint32_t* p = &Bsf[st][nt][kc][0][reg];
                p[(lane0 + 0) * 2]  = f2tf32(pb[l].x);
                p[(lane0 + 4) * 2]  = f2tf32(pb[l].y);
                p[(lane0 + 8) * 2]  = f2tf32(pb[l].z);
                p[(lane0 + 12) * 2] = f2tf32(pb[l].w);
            } else {
                int n = i >> 2, kq = i & 3;                   // n-row, k-quad
                int kc = kq >> 1, reg = kq & 1;
                int nt = n >> 3;
                int lane0 = (n & 7) * 4;
                uint32_t* p = &Bsf[st][nt][kc][lane0][reg];
                p[0] = f2tf32(pb[l].x);
                p[2] = f2tf32(pb[l].y);
                p[4] = f2tf32(pb[l].z);
                p[6] = f2tf32(pb[l].w);
            }
        }
    };

    g_load(0);
    s_store(0);
    __syncthreads();

    const int kt = K / BK;
    for (int t = 0; t < kt; t++) {
        const int st = t & 1;
        if (t + 1 < kt) g_load((t + 1) * BK);
#pragma unroll
        for (int kc = 0; kc < 2; kc++) {
            uint32_t af[FM][4], bf[FN][2];
#pragma unroll
            for (int i = 0; i < FM; i++)
                *(uint4*)af[i] = *(const uint4*)&Asf[st][wm * FM + i][kc][lane][0];
#pragma unroll
            for (int j = 0; j < FN; j++)
                *(uint2*)bf[j] = *(const uint2*)&Bsf[st][wn * FN + j][kc][lane][0];
#pragma unroll
            for (int i = 0; i < FM; i++)
#pragma unroll
                for (int j = 0; j < FN; j++) mma_tf32(acc[i][j], af[i], bf[j]);
        }
        if (t + 1 < kt) s_store((t + 1) & 1);
        __syncthreads();
    }

    // ---- epilogue ----
#pragma unroll
    for (int i = 0; i < FM; i++) {
        int r0 = row0 + wm * WTM + i * 16 + grp;
#pragma unroll
        for (int j = 0; j < FN; j++) {
            int c = col0 + wn * WTN + j * 8 + qid * 2;
            float2 v0 = {acc[i][j][0] * alpha, acc[i][j][1] * alpha};
            float2 v1 = {acc[i][j][2] * alpha, acc[i][j][3] * alpha};
            if (RESID) {
                int rr0 = RMOD ? (r0 % RMOD) : r0;
                int rr1 = RMOD ? ((r0 + 8) % RMOD) : (r0 + 8);
                float2 r0v = *(const float2*)(R + (long)rr0 * Nn + c);
                float2 r1v = *(const float2*)(R + (long)rr1 * Nn + c);
                v0.x += beta * r0v.x; v0.y += beta * r0v.y;
                v1.x += beta * r1v.x; v1.y += beta * r1v.y;
            }
            *(float2*)(C + (long)r0 * Nn + c) = v0;
            *(float2*)(C + (long)(r0 + 8) * Nn + c) = v1;
        }
    }
}

// ---------------- row softmax over 512 (one warp per row) -------------------
__global__ __launch_bounds__(256) void softmax_kernel() {
    long row = (long)blockIdx.x * 8 + (threadIdx.x >> 5);
    int lane = threadIdx.x & 31;
    if (row >= (long)B_ * Q_ * N_) return;
    float* p = g_S + row * N_;
    float vals[16];
    float m = -1e30f;
#pragma unroll
    for (int i = 0; i < 16; i++) {
        vals[i] = p[lane + i * 32];
        m = fmaxf(m, vals[i]);
    }
#pragma unroll
    for (int o = 16; o; o >>= 1) m = fmaxf(m, __shfl_xor_sync(0xffffffffu, m, o));
    float s = 0.f;
#pragma unroll
    for (int i = 0; i < 16; i++) {
        vals[i] = __expf(vals[i] - m);
        s += vals[i];
    }
#pragma unroll
    for (int o = 16; o; o >>= 1) s += __shfl_xor_sync(0xffffffffu, s, o);
    float inv = 1.f / s;
#pragma unroll
    for (int i = 0; i < 16; i++) p[lane + i * 32] = vals[i] * inv;
}

// ---------------- launch ----------------------------------------------------
extern "C" void kernel_launch(void* const* d_in, const int* in_sizes, int n_in,
                              void* d_out, int out_size) {
    const float* inputs = (const float*)d_in[0];
    const float* W_in  = (const float*)d_in[2];
    const float* T_mix = (const float*)d_in[3];
    const float* Wq    = (const float*)d_in[4];
    const float* Wk    = (const float*)d_in[5];
    const float* Wv    = (const float*)d_in[6];
    const float* W_out = (const float*)d_in[7];
    const float* A     = (const float*)d_in[8];

    float* out = (float*)d_out;
    float* mgt = out;                                   // (B,Q,N,F)
    float* kal = out + (long)B_ * Q_ * N_ * F_;         // (B,Q,N,F)

    float *tmp, *h, *qb, *kb, *vb, *S, *CP;
    cudaGetSymbolAddress((void**)&tmp, g_tmp);
    cudaGetSymbolAddress((void**)&h, g_h);
    cudaGetSymbolAddress((void**)&qb, g_q);
    cudaGetSymbolAddress((void**)&kb, g_k);
    cudaGetSymbolAddress((void**)&vb, g_v);
    cudaGetSymbolAddress((void**)&S, g_S);
    cudaGetSymbolAddress((void**)&CP, g_CP);

    const long sND = (long)N_ * D_;
    const long sNN = (long)N_ * N_;
    const long sNF = (long)N_ * F_;
    const int nBatch = B_ * Q_;   // 384

    // K1: time-mix (B,P,N,F) -> (B,Q,N,F)
    mix_kernel<<<((long)B_ * N_ * F_ + 255) / 256, 256>>>(inputs, T_mix);

    // Kalman setup: CP[0] = DT*A ; CP[1] = C2 = DT^2*(A@A) + 2*DT*A
    scaleA_kernel<<<(N_ * N_ + 255) / 256, 256>>>(A);
    gemm_tc<128, 256, 2, 4, false, true, 0><<<dim3(2, 4, 1), 256>>>(
        A, A, CP + (long)N_ * N_, A, N_, N_, N_, 0, 0, 0, 0, DT_ * DT_, 2.f * DT_);

    // K2: h = tmp @ W_in   (M=196608, N=256, K=64)
    gemm_tc<128, 256, 2, 4, false, false, 0><<<dim3(1, BQN / 128, 1), 256>>>(
        tmp, W_in, h, nullptr, BQN, D_, F_, 0, 0, 0, 0, 1.f, 0.f);

    // K3: q/k/v = h @ W{q,k,v}
    gemm_tc<128, 256, 2, 4, false, false, 0><<<dim3(1, BQN / 128, 1), 256>>>(
        h, Wq, qb, nullptr, BQN, D_, D_, 0, 0, 0, 0, 0.0625f, 0.f);
    gemm_tc<128, 256, 2, 4, false, false, 0><<<dim3(1, BQN / 128, 1), 256>>>(
        h, Wk, kb, nullptr, BQN, D_, D_, 0, 0, 0, 0, 1.f, 0.f);
    gemm_tc<128, 256, 2, 4, false, false, 0><<<dim3(1, BQN / 128, 1), 256>>>(
        h, Wv, vb, nullptr, BQN, D_, D_, 0, 0, 0, 0, 1.f, 0.f);

    // K4: S = q @ k^T  batched   (512x512x256, NT)
    gemm_tc<128, 256, 2, 4, true, false, 0><<<dim3(2, 4, nBatch), 256>>>(
        qb, kb, S, nullptr, N_, N_, D_, sND, sND, sNN, 0, 1.f, 0.f);

    // K5: row softmax
    softmax_kernel<<<(BQN + 7) / 8, 256>>>();

    // K6: h = h + S @ v   batched   (512x256x512, NN, residual)
    gemm_tc<128, 256, 2, 4, false, true, 0><<<dim3(1, 4, nBatch), 256>>>(
        S, vb, h, h, N_, D_, N_, sNN, sND, sND, sND, 1.f, 1.f);

    // K7: mgt = h @ W_out   (M=196608, N=64, K=256)
    gemm_tc<128, 64, 2, 2, false, false, 0><<<dim3(1, BQN / 128, 1), 128>>>(
        h, W_out, mgt, nullptr, BQN, F_, D_, 0, 0, 0, 0, 1.f, 0.f);

    // Kalman: [mu_{t+1}; mu_{t+2}] = CP @ mu_t + mu_t  (6 double-steps)
    // Residual form keeps the identity exact in fp32; tf32 error only on the
    // small correction terms.
    for (int s = 0; s < Q_ / 2; s++) {
        const float* prev;
        long sB;
        if (s == 0) {
            prev = inputs + (long)(P_ - 1) * sNF;   // inputs[:, -1]
            sB = (long)P_ * sNF;
        } else {
            prev = kal + (long)(2 * s - 1) * sNF;
            sB = (long)Q_ * sNF;
        }
        // M = 2*N = 1024 rows; C rows map contiguously onto kal[(2s)..(2s+1)]
        gemm_tc<128, 64, 2, 2, false, true, N_><<<dim3(1, 8, B_), 128>>>(
            CP, prev, kal + (long)(2 * s) * sNF, prev,
            2 * N_, F_, N_, 0, sB, (long)Q_ * sNF, sB, 1.f, 1.f);
    }
}

// round 4
// speedup vs baseline: 2.2319x; 2.2319x over previous
#include <cuda_runtime.h>
#include <cstdint>

// Problem dims
#define B_ 32
#define P_ 12
#define N_ 512
#define F_ 64
#define D_ 256
#define Q_ 12
#define DT_ 0.1f

static const int BQN = B_ * Q_ * N_;  // 196608

// ---------------- scratch (device globals; no runtime alloc) ----------------
__device__ float g_tmp [(size_t)B_ * Q_ * N_ * F_];     // mixed inputs (B,Q,N,F)
__device__ float g_h   [(size_t)B_ * Q_ * N_ * D_];     // hidden       (B,Q,N,D)
__device__ float g_qkv [(size_t)B_ * Q_ * N_ * 3 * D_]; // q|k|v interleaved, ld=768
__device__ float g_S   [(size_t)B_ * Q_ * N_ * N_];     // scores/attn  (B,Q,N,N)
__device__ float g_CP  [(size_t)2 * N_ * N_];           // [DT*A ; DT^2*A^2+2DT*A]
__device__ float g_Wqkv[(size_t)D_ * 3 * D_];           // [Wq/16 | Wk | Wv]

// ---------------- helpers ----------------------------------------------------
__device__ __forceinline__ uint32_t f2tf32(float f) {
    uint32_t u;
    asm("cvt.rna.tf32.f32 %0, %1;" : "=r"(u) : "f"(f));
    return u;
}

__device__ __forceinline__ void mma_tf32(float* c, const uint32_t* a, const uint32_t* b) {
    asm volatile(
        "mma.sync.aligned.m16n8k8.row.col.f32.tf32.tf32.f32 "
        "{%0,%1,%2,%3}, {%4,%5,%6,%7}, {%8,%9}, {%0,%1,%2,%3};"
        : "+f"(c[0]), "+f"(c[1]), "+f"(c[2]), "+f"(c[3])
        : "r"(a[0]), "r"(a[1]), "r"(a[2]), "r"(a[3]),
          "r"(b[0]), "r"(b[1]));
}

// ---------------- K1: tmp[b,q,n,f] = sum_p inputs[b,p,n,f] * T_mix[p,q] -----
__global__ __launch_bounds__(256) void mix_kernel(const float* __restrict__ in,
                                                  const float* __restrict__ T) {
    __shared__ float Ts[P_][Q_];
    int t = threadIdx.x;
    if (t < P_ * Q_) Ts[t / Q_][t % Q_] = T[t];
    __syncthreads();
    long idx = (long)blockIdx.x * blockDim.x + t;          // over B*N*F
    if (idx >= (long)B_ * N_ * F_) return;
    int f = (int)(idx % F_);
    int n = (int)((idx / F_) % N_);
    int b = (int)(idx / ((long)F_ * N_));
    float vals[P_];
    const float* ip = in + ((long)b * P_ * N_ + n) * F_ + f;
#pragma unroll
    for (int p = 0; p < P_; p++) vals[p] = ip[(long)p * N_ * F_];
    float* op = g_tmp + ((long)b * Q_ * N_ + n) * F_ + f;
#pragma unroll
    for (int q = 0; q < Q_; q++) {
        float s = 0.f;
#pragma unroll
        for (int p = 0; p < P_; p++) s += vals[p] * Ts[p][q];
        op[(long)q * N_ * F_] = s;
    }
}

// ---------------- setup: Wqkv concat, CP[0] = DT*A ---------------------------
__global__ __launch_bounds__(256) void concat_w(const float* __restrict__ Wq,
                                                const float* __restrict__ Wk,
                                                const float* __restrict__ Wv) {
    int i = blockIdx.x * blockDim.x + threadIdx.x;
    if (i < D_ * D_) {
        int r = i / D_, c = i % D_;
        g_Wqkv[(long)r * 3 * D_ + c]           = Wq[i] * 0.0625f;  // fold 1/sqrt(D)
        g_Wqkv[(long)r * 3 * D_ + D_ + c]      = Wk[i];
        g_Wqkv[(long)r * 3 * D_ + 2 * D_ + c]  = Wv[i];
    }
}

__global__ __launch_bounds__(256) void scaleA_kernel(const float* __restrict__ A) {
    int i = blockIdx.x * blockDim.x + threadIdx.x;
    if (i < N_ * N_) g_CP[i] = DT_ * A[i];
}

// ---------------- tf32 tensor-core GEMM (R2 layout + double buffer) ----------
// C = alpha * A * op(B) + beta * R (if RESID).  A: M x K, leading dim lda.
// NN: B is K x Nn (ldb).  NT: B is Nn x K (ldb), C = A*B^T.
// Batched via blockIdx.z with strides sA/sB/sC/sR.
// RMOD>0: residual row index is (row % RMOD).
// Warp tile 64 x (BN/WN). Requires M%BM==0, Nn%BN==0, K%16==0.
template <int BM, int BN, int WM, int WN, bool TRANS_B, bool RESID, int RMOD>
__global__ __launch_bounds__(WM* WN * 32) void gemm_tc(
    const float* __restrict__ A, const float* __restrict__ Bm,
    float* __restrict__ C, const float* __restrict__ R,
    int M, int Nn, int K, int lda, int ldb, int ldc, int ldr,
    long sA, long sB, long sC, long sR, float alpha, float beta) {
    constexpr int BK = 16;
    constexpr int NT = WM * WN * 32;
    constexpr int WTM = BM / WM;           // 64
    constexpr int WTN = BN / WN;           // 32
    constexpr int FM = WTM / 16;           // 4
    constexpr int FN = WTN / 8;            // 4
    constexpr int LDA_S = BK + 4;          // 20: conflict-free frag reads
    constexpr int LDB_S = BN + 8;          // mod 32 == 8: conflict-free reads
    constexpr int NA4 = BM * BK / (4 * NT);
    constexpr int NB4 = BN * BK / (4 * NT);

    __shared__ __align__(16) uint32_t As[2][BM][LDA_S];   // [m][k]
    __shared__ __align__(16) uint32_t Bs[2][BK][LDB_S];   // [k][n]

    const int bz = blockIdx.z;
    A += (long)bz * sA;
    Bm += (long)bz * sB;
    C += (long)bz * sC;
    if (RESID) R += (long)bz * sR;

    const int row0 = blockIdx.y * BM, col0 = blockIdx.x * BN;
    const int tid = threadIdx.x;
    const int lane = tid & 31, wid = tid >> 5;
    const int grp = lane >> 2, qid = lane & 3;
    const int wm = wid / WN, wn = wid % WN;
    const int m_base = wm * WTM, n_base = wn * WTN;

    float acc[FM][FN][4] = {};
    float4 pa[NA4], pb[NB4];

    auto g_load = [&](int k0) {
#pragma unroll
        for (int l = 0; l < NA4; l++) {
            int i = tid + l * NT;
            int r = i >> 2, kq = i & 3;
            pa[l] = *(const float4*)(A + (long)(row0 + r) * lda + k0 + kq * 4);
        }
#pragma unroll
        for (int l = 0; l < NB4; l++) {
            int i = tid + l * NT;
            if (!TRANS_B) {
                int kk = i / (BN / 4), nq = i % (BN / 4);
                pb[l] = *(const float4*)(Bm + (long)(k0 + kk) * ldb + col0 + nq * 4);
            } else {
                int n = i >> 2, kq = i & 3;
                pb[l] = *(const float4*)(Bm + (long)(col0 + n) * ldb + k0 + kq * 4);
            }
        }
    };
    auto s_store = [&](int st) {
#pragma unroll
        for (int l = 0; l < NA4; l++) {
            int i = tid + l * NT;
            int r = i >> 2, kq = i & 3;
            uint4 u = {f2tf32(pa[l].x), f2tf32(pa[l].y), f2tf32(pa[l].z), f2tf32(pa[l].w)};
            *(uint4*)&As[st][r][kq * 4] = u;
        }
#pragma unroll
        for (int l = 0; l < NB4; l++) {
            int i = tid + l * NT;
            if (!TRANS_B) {
                int kk = i / (BN / 4), nq = i % (BN / 4);
                uint4 u = {f2tf32(pb[l].x), f2tf32(pb[l].y), f2tf32(pb[l].z), f2tf32(pb[l].w)};
                *(uint4*)&Bs[st][kk][nq * 4] = u;
            } else {
                int n = i >> 2, kq = i & 3;
                Bs[st][kq * 4 + 0][n] = f2tf32(pb[l].x);
                Bs[st][kq * 4 + 1][n] = f2tf32(pb[l].y);
                Bs[st][kq * 4 + 2][n] = f2tf32(pb[l].z);
                Bs[st][kq * 4 + 3][n] = f2tf32(pb[l].w);
            }
        }
    };

    g_load(0);
    s_store(0);
    __syncthreads();

    const int kt = K / BK;
    for (int t = 0; t < kt; t++) {
        const int st = t & 1;
        if (t + 1 < kt) g_load((t + 1) * BK);
#pragma unroll
        for (int kc = 0; kc < 2; kc++) {
            const int kk = kc * 8;
            uint32_t af[FM][4], bf[FN][2];
#pragma unroll
            for (int i = 0; i < FM; i++) {
                int m = m_base + i * 16 + grp;
                af[i][0] = As[st][m][kk + qid];
                af[i][1] = As[st][m + 8][kk + qid];
                af[i][2] = As[st][m][kk + qid + 4];
                af[i][3] = As[st][m + 8][kk + qid + 4];
            }
#pragma unroll
            for (int j = 0; j < FN; j++) {
                int n = n_base + j * 8 + grp;
                bf[j][0] = Bs[st][kk + qid][n];
                bf[j][1] = Bs[st][kk + qid + 4][n];
            }
#pragma unroll
            for (int i = 0; i < FM; i++)
#pragma unroll
                for (int j = 0; j < FN; j++) mma_tf32(acc[i][j], af[i], bf[j]);
        }
        if (t + 1 < kt) s_store(st ^ 1);   // write inactive buffer: no pre-sync needed
        __syncthreads();
    }

    // ---- epilogue ----
#pragma unroll
    for (int i = 0; i < FM; i++) {
        int r0 = row0 + m_base + i * 16 + grp;
#pragma unroll
        for (int j = 0; j < FN; j++) {
            int c = col0 + n_base + j * 8 + qid * 2;
            float2 v0 = {acc[i][j][0] * alpha, acc[i][j][1] * alpha};
            float2 v1 = {acc[i][j][2] * alpha, acc[i][j][3] * alpha};
            if (RESID) {
                int rr0 = RMOD ? (r0 % RMOD) : r0;
                int rr1 = RMOD ? ((r0 + 8) % RMOD) : (r0 + 8);
                float2 r0v = *(const float2*)(R + (long)rr0 * ldr + c);
                float2 r1v = *(const float2*)(R + (long)rr1 * ldr + c);
                v0.x += beta * r0v.x; v0.y += beta * r0v.y;
                v1.x += beta * r1v.x; v1.y += beta * r1v.y;
            }
            *(float2*)(C + (long)r0 * ldc + c) = v0;
            *(float2*)(C + (long)(r0 + 8) * ldc + c) = v1;
        }
    }
}

// ---------------- row softmax over 512 (one warp per row) -------------------
__global__ __launch_bounds__(256) void softmax_kernel() {
    long row = (long)blockIdx.x * 8 + (threadIdx.x >> 5);
    int lane = threadIdx.x & 31;
    if (row >= (long)B_ * Q_ * N_) return;
    float* p = g_S + row * N_;
    float vals[16];
    float m = -1e30f;
#pragma unroll
    for (int i = 0; i < 16; i++) {
        vals[i] = p[lane + i * 32];
        m = fmaxf(m, vals[i]);
    }
#pragma unroll
    for (int o = 16; o; o >>= 1) m = fmaxf(m, __shfl_xor_sync(0xffffffffu, m, o));
    float s = 0.f;
#pragma unroll
    for (int i = 0; i < 16; i++) {
        vals[i] = __expf(vals[i] - m);
        s += vals[i];
    }
#pragma unroll
    for (int o = 16; o; o >>= 1) s += __shfl_xor_sync(0xffffffffu, s, o);
    float inv = 1.f / s;
#pragma unroll
    for (int i = 0; i < 16; i++) p[lane + i * 32] = vals[i] * inv;
}

// ---------------- launch ----------------------------------------------------
extern "C" void kernel_launch(void* const* d_in, const int* in_sizes, int n_in,
                              void* d_out, int out_size) {
    const float* inputs = (const float*)d_in[0];
    const float* W_in  = (const float*)d_in[2];
    const float* T_mix = (const float*)d_in[3];
    const float* Wq    = (const float*)d_in[4];
    const float* Wk    = (const float*)d_in[5];
    const float* Wv    = (const float*)d_in[6];
    const float* W_out = (const float*)d_in[7];
    const float* A     = (const float*)d_in[8];

    float* out = (float*)d_out;
    float* mgt = out;                                   // (B,Q,N,F)
    float* kal = out + (long)B_ * Q_ * N_ * F_;         // (B,Q,N,F)

    float *tmp, *h, *qkv, *S, *CP, *Wqkv;
    cudaGetSymbolAddress((void**)&tmp, g_tmp);
    cudaGetSymbolAddress((void**)&h, g_h);
    cudaGetSymbolAddress((void**)&qkv, g_qkv);
    cudaGetSymbolAddress((void**)&S, g_S);
    cudaGetSymbolAddress((void**)&CP, g_CP);
    cudaGetSymbolAddress((void**)&Wqkv, g_Wqkv);

    const long sNN = (long)N_ * N_;
    const long sNF = (long)N_ * F_;
    const long sQKV = (long)N_ * 3 * D_;   // per-(b,q) stride in qkv buffer
    const long sH = (long)N_ * D_;
    const int nBatch = B_ * Q_;            // 384

    // K1: time-mix
    mix_kernel<<<((long)B_ * N_ * F_ + 255) / 256, 256>>>(inputs, T_mix);

    // setup: Wqkv concat ; CP = [DT*A ; DT^2*A@A + 2DT*A]
    concat_w<<<(D_ * D_ + 255) / 256, 256>>>(Wq, Wk, Wv);
    scaleA_kernel<<<(N_ * N_ + 255) / 256, 256>>>(A);
    gemm_tc<128, 128, 2, 4, false, true, 0><<<dim3(4, 4, 1), 256>>>(
        A, A, CP + sNN, A, N_, N_, N_, N_, N_, N_, N_,
        0, 0, 0, 0, DT_ * DT_, 2.f * DT_);

    // K2: h = tmp @ W_in   (M=196608, N=256, K=64)
    gemm_tc<128, 128, 2, 4, false, false, 0><<<dim3(2, BQN / 128, 1), 256>>>(
        tmp, W_in, h, nullptr, BQN, D_, F_, F_, D_, D_, 0,
        0, 0, 0, 0, 1.f, 0.f);

    // K3: qkv = h @ Wqkv   (M=196608, N=768, K=256); q pre-scaled in Wqkv
    gemm_tc<128, 128, 2, 4, false, false, 0><<<dim3(6, BQN / 128, 1), 256>>>(
        h, Wqkv, qkv, nullptr, BQN, 3 * D_, D_, D_, 3 * D_, 3 * D_, 0,
        0, 0, 0, 0, 1.f, 0.f);

    // K4: S = q @ k^T   batched (512x512x256, NT); q at col 0, k at col 256
    gemm_tc<128, 128, 2, 4, true, false, 0><<<dim3(4, 4, nBatch), 256>>>(
        qkv, qkv + D_, S, nullptr, N_, N_, D_, 3 * D_, 3 * D_, N_, 0,
        sQKV, sQKV, sNN, 0, 1.f, 0.f);

    // K5: row softmax
    softmax_kernel<<<(BQN + 7) / 8, 256>>>();

    // K6: h = h + S @ v   batched (512x256x512, NN, residual); v at col 512
    gemm_tc<128, 128, 2, 4, false, true, 0><<<dim3(2, 4, nBatch), 256>>>(
        S, qkv + 2 * D_, h, h, N_, D_, N_, N_, 3 * D_, D_, D_,
        sNN, sQKV, sH, sH, 1.f, 1.f);

    // K7: mgt = h @ W_out   (M=196608, N=64, K=256)
    gemm_tc<128, 64, 2, 2, false, false, 0><<<dim3(1, BQN / 128, 1), 128>>>(
        h, W_out, mgt, nullptr, BQN, F_, D_, D_, F_, F_, 0,
        0, 0, 0, 0, 1.f, 0.f);

    // Kalman: [mu_{t+1}; mu_{t+2}] = CP @ mu_t + mu_t  (6 double-steps).
    // Residual form keeps the identity exact in fp32; tf32 only touches the
    // small DT-scaled corrections.
    for (int s = 0; s < Q_ / 2; s++) {
        const float* prev;
        long sB;
        if (s == 0) {
            prev = inputs + (long)(P_ - 1) * sNF;   // inputs[:, -1]
            sB = (long)P_ * sNF;
        } else {
            prev = kal + (long)(2 * s - 1) * sNF;
            sB = (long)Q_ * sNF;
        }
        gemm_tc<128, 64, 2, 2, false, true, N_><<<dim3(1, 8, B_), 128>>>(
            CP, prev, kal + (long)(2 * s) * sNF, prev,
            2 * N_, F_, N_, N_, F_, F_, F_,
            0, sB, (long)Q_ * sNF, sB, 1.f, 1.f);
    }
}

// round 5
// speedup vs baseline: 2.3825x; 1.0675x over previous
#include <cuda_runtime.h>
#include <cstdint>

// Problem dims
#define B_ 32
#define P_ 12
#define N_ 512
#define F_ 64
#define D_ 256
#define Q_ 12
#define DT_ 0.1f

static const int BQN = B_ * Q_ * N_;  // 196608

// ---------------- scratch (device globals; no runtime alloc) ----------------
__device__ float g_tmp [(size_t)B_ * Q_ * N_ * F_];     // mixed inputs (B,Q,N,F)
__device__ float g_h   [(size_t)B_ * Q_ * N_ * D_];     // hidden       (B,Q,N,D)
__device__ float g_qkv [(size_t)B_ * Q_ * N_ * 3 * D_]; // q|k|v interleaved, ld=768
__device__ float g_S   [(size_t)B_ * Q_ * N_ * N_];     // scores/attn  (B,Q,N,N)
__device__ float g_CP  [(size_t)2 * N_ * N_];           // [DT*A ; DT^2*A^2+2DT*A]
__device__ float g_Wqkv[(size_t)D_ * 3 * D_];           // [Wq/16 | Wk | Wv]

// ---------------- helpers ----------------------------------------------------
__device__ __forceinline__ uint32_t f2tf32(float f) {
    uint32_t u;
    asm("cvt.rna.tf32.f32 %0, %1;" : "=r"(u) : "f"(f));
    return u;
}

__device__ __forceinline__ void mma_tf32(float* c, const uint32_t* a, const uint32_t* b) {
    asm volatile(
        "mma.sync.aligned.m16n8k8.row.col.f32.tf32.tf32.f32 "
        "{%0,%1,%2,%3}, {%4,%5,%6,%7}, {%8,%9}, {%0,%1,%2,%3};"
        : "+f"(c[0]), "+f"(c[1]), "+f"(c[2]), "+f"(c[3])
        : "r"(a[0]), "r"(a[1]), "r"(a[2]), "r"(a[3]),
          "r"(b[0]), "r"(b[1]));
}

__device__ __forceinline__ void cp_async16(void* smem_dst, const void* gsrc) {
    uint32_t dst = (uint32_t)__cvta_generic_to_shared(smem_dst);
    asm volatile("cp.async.cg.shared.global [%0], [%1], 16;\n" :: "r"(dst), "l"(gsrc));
}

// ---------------- K1: tmp[b,q,n,f] = sum_p inputs[b,p,n,f] * T_mix[p,q] -----
__global__ __launch_bounds__(256) void mix_kernel(const float* __restrict__ in,
                                                  const float* __restrict__ T) {
    __shared__ float Ts[P_][Q_];
    int t = threadIdx.x;
    if (t < P_ * Q_) Ts[t / Q_][t % Q_] = T[t];
    __syncthreads();
    long idx = (long)blockIdx.x * blockDim.x + t;          // over B*N*F
    if (idx >= (long)B_ * N_ * F_) return;
    int f = (int)(idx % F_);
    int n = (int)((idx / F_) % N_);
    int b = (int)(idx / ((long)F_ * N_));
    float vals[P_];
    const float* ip = in + ((long)b * P_ * N_ + n) * F_ + f;
#pragma unroll
    for (int p = 0; p < P_; p++) vals[p] = ip[(long)p * N_ * F_];
    float* op = g_tmp + ((long)b * Q_ * N_ + n) * F_ + f;
#pragma unroll
    for (int q = 0; q < Q_; q++) {
        float s = 0.f;
#pragma unroll
        for (int p = 0; p < P_; p++) s += vals[p] * Ts[p][q];
        op[(long)q * N_ * F_] = s;
    }
}

// ---------------- setup: Wqkv concat, CP[0] = DT*A ---------------------------
__global__ __launch_bounds__(256) void concat_w(const float* __restrict__ Wq,
                                                const float* __restrict__ Wk,
                                                const float* __restrict__ Wv) {
    int i = blockIdx.x * blockDim.x + threadIdx.x;
    if (i < D_ * D_) {
        int r = i / D_, c = i % D_;
        g_Wqkv[(long)r * 3 * D_ + c]           = Wq[i] * 0.0625f;  // fold 1/sqrt(D)
        g_Wqkv[(long)r * 3 * D_ + D_ + c]      = Wk[i];
        g_Wqkv[(long)r * 3 * D_ + 2 * D_ + c]  = Wv[i];
    }
}

__global__ __launch_bounds__(256) void scaleA_kernel(const float* __restrict__ A) {
    int i = blockIdx.x * blockDim.x + threadIdx.x;
    if (i < N_ * N_) g_CP[i] = DT_ * A[i];
}

// ---------------- tf32 tensor-core GEMM, 3-stage cp.async pipeline -----------
// C = alpha * A * op(B) + beta * R (if RESID).  A: M x K (lda).
// NN: B is K x Nn (ldb).  NT: B is Nn x K (ldb), C = A*B^T.
// Batched via blockIdx.z with strides. RMOD>0: residual row = (row % RMOD).
// smem holds raw fp32; tf32 cvt happens at fragment-read time.
template <int BM, int BN, int WM, int WN, bool TRANS_B, bool RESID, int RMOD>
__global__ __launch_bounds__(WM* WN * 32, 2) void gemm_tc(
    const float* __restrict__ A, const float* __restrict__ Bm,
    float* __restrict__ C, const float* __restrict__ R,
    int M, int Nn, int K, int lda, int ldb, int ldc, int ldr,
    long sA, long sB, long sC, long sR, float alpha, float beta) {
    constexpr int BK = 16;
    constexpr int STAGES = 3;
    constexpr int NTH = WM * WN * 32;
    constexpr int WTM = BM / WM;           // 64
    constexpr int WTN = BN / WN;           // 32
    constexpr int FM = WTM / 16;           // 4
    constexpr int FN = WTN / 8;            // 4
    constexpr int LDA_S = BK + 4;          // 20: conflict-free (all 32 banks hit)
    constexpr int LDB_S = BN + 8;
    constexpr int NA = BM * BK / (4 * NTH);
    constexpr int NB = (TRANS_B ? BN * BK : BK * BN) / (4 * NTH);

    extern __shared__ __align__(16) float smem[];
    float* As_ = smem;                                // [STAGES][BM][LDA_S]
    float* Bs_ = smem + STAGES * BM * LDA_S;          // NN: [STAGES][BK][LDB_S]
                                                      // NT: [STAGES][BN][LDA_S]
    const int bz = blockIdx.z;
    A += (long)bz * sA;
    Bm += (long)bz * sB;
    C += (long)bz * sC;
    if (RESID) R += (long)bz * sR;

    const int row0 = blockIdx.y * BM, col0 = blockIdx.x * BN;
    const int tid = threadIdx.x;
    const int lane = tid & 31, wid = tid >> 5;
    const int grp = lane >> 2, qid = lane & 3;
    const int wm = wid / WN, wn = wid % WN;
    const int m_base = wm * WTM, n_base = wn * WTN;

    float acc[FM][FN][4] = {};

    auto issue = [&](int st, int k0) {
#pragma unroll
        for (int l = 0; l < NA; l++) {
            int i = tid + l * NTH;
            int r = i >> 2, kq = i & 3;
            cp_async16(&As_[(st * BM + r) * LDA_S + kq * 4],
                       A + (long)(row0 + r) * lda + k0 + kq * 4);
        }
#pragma unroll
        for (int l = 0; l < NB; l++) {
            int i = tid + l * NTH;
            if (!TRANS_B) {
                int kk = i / (BN / 4), nq = i % (BN / 4);
                cp_async16(&Bs_[(st * BK + kk) * LDB_S + nq * 4],
                           Bm + (long)(k0 + kk) * ldb + col0 + nq * 4);
            } else {
                int n = i >> 2, kq = i & 3;
                cp_async16(&Bs_[(st * BN + n) * LDA_S + kq * 4],
                           Bm + (long)(col0 + n) * ldb + k0 + kq * 4);
            }
        }
    };

    const int kt = K / BK;
#pragma unroll
    for (int s = 0; s < STAGES - 1; s++) {
        issue(s, s * BK);
        asm volatile("cp.async.commit_group;\n");
    }

    for (int t = 0; t < kt; t++) {
        asm volatile("cp.async.wait_group %0;\n" :: "n"(STAGES - 2));
        __syncthreads();
        const int st = t % STAGES;
        const int nx = t + STAGES - 1;
        if (nx < kt) issue(nx % STAGES, nx * BK);   // writes stage computed at t-1
        asm volatile("cp.async.commit_group;\n");

#pragma unroll
        for (int kc = 0; kc < 2; kc++) {
            const int kk = kc * 8;
            uint32_t af[FM][4], bf[FN][2];
#pragma unroll
            for (int i = 0; i < FM; i++) {
                const float* pA = &As_[(st * BM + m_base + i * 16 + grp) * LDA_S];
                af[i][0] = f2tf32(pA[kk + qid]);
                af[i][1] = f2tf32(pA[8 * LDA_S + kk + qid]);
                af[i][2] = f2tf32(pA[kk + qid + 4]);
                af[i][3] = f2tf32(pA[8 * LDA_S + kk + qid + 4]);
            }
#pragma unroll
            for (int j = 0; j < FN; j++) {
                int n = n_base + j * 8 + grp;
                if (!TRANS_B) {
                    bf[j][0] = f2tf32(Bs_[(st * BK + kk + qid) * LDB_S + n]);
                    bf[j][1] = f2tf32(Bs_[(st * BK + kk + qid + 4) * LDB_S + n]);
                } else {
                    const float* pB = &Bs_[(st * BN + n) * LDA_S];
                    bf[j][0] = f2tf32(pB[kk + qid]);
                    bf[j][1] = f2tf32(pB[kk + qid + 4]);
                }
            }
#pragma unroll
            for (int i = 0; i < FM; i++)
#pragma unroll
                for (int j = 0; j < FN; j++) mma_tf32(acc[i][j], af[i], bf[j]);
        }
    }

    // ---- epilogue ----
#pragma unroll
    for (int i = 0; i < FM; i++) {
        int r0 = row0 + m_base + i * 16 + grp;
#pragma unroll
        for (int j = 0; j < FN; j++) {
            int c = col0 + n_base + j * 8 + qid * 2;
            float2 v0 = {acc[i][j][0] * alpha, acc[i][j][1] * alpha};
            float2 v1 = {acc[i][j][2] * alpha, acc[i][j][3] * alpha};
            if (RESID) {
                int rr0 = RMOD ? (r0 % RMOD) : r0;
                int rr1 = RMOD ? ((r0 + 8) % RMOD) : (r0 + 8);
                float2 r0v = *(const float2*)(R + (long)rr0 * ldr + c);
                float2 r1v = *(const float2*)(R + (long)rr1 * ldr + c);
                v0.x += beta * r0v.x; v0.y += beta * r0v.y;
                v1.x += beta * r1v.x; v1.y += beta * r1v.y;
            }
            *(float2*)(C + (long)r0 * ldc + c) = v0;
            *(float2*)(C + (long)(r0 + 8) * ldc + c) = v1;
        }
    }
}

// host-side smem size mirror
static inline int gemm_smem_bytes(int BM, int BN, bool transB) {
    const int STAGES = 3, BK = 16, LDA_S = 20;
    int a = STAGES * BM * LDA_S;
    int b = transB ? STAGES * BN * LDA_S : STAGES * BK * (BN + 8);
    return (a + b) * 4;
}

// ---------------- row softmax over 512 (one warp per row) -------------------
__global__ __launch_bounds__(256) void softmax_kernel() {
    long row = (long)blockIdx.x * 8 + (threadIdx.x >> 5);
    int lane = threadIdx.x & 31;
    if (row >= (long)B_ * Q_ * N_) return;
    float* p = g_S + row * N_;
    float vals[16];
    float m = -1e30f;
#pragma unroll
    for (int i = 0; i < 16; i++) {
        vals[i] = p[lane + i * 32];
        m = fmaxf(m, vals[i]);
    }
#pragma unroll
    for (int o = 16; o; o >>= 1) m = fmaxf(m, __shfl_xor_sync(0xffffffffu, m, o));
    float s = 0.f;
#pragma unroll
    for (int i = 0; i < 16; i++) {
        vals[i] = __expf(vals[i] - m);
        s += vals[i];
    }
#pragma unroll
    for (int o = 16; o; o >>= 1) s += __shfl_xor_sync(0xffffffffu, s, o);
    float inv = 1.f / s;
#pragma unroll
    for (int i = 0; i < 16; i++) p[lane + i * 32] = vals[i] * inv;
}

// ---------------- launch ----------------------------------------------------
extern "C" void kernel_launch(void* const* d_in, const int* in_sizes, int n_in,
                              void* d_out, int out_size) {
    const float* inputs = (const float*)d_in[0];
    const float* W_in  = (const float*)d_in[2];
    const float* T_mix = (const float*)d_in[3];
    const float* Wq    = (const float*)d_in[4];
    const float* Wk    = (const float*)d_in[5];
    const float* Wv    = (const float*)d_in[6];
    const float* W_out = (const float*)d_in[7];
    const float* A     = (const float*)d_in[8];

    float* out = (float*)d_out;
    float* mgt = out;                                   // (B,Q,N,F)
    float* kal = out + (long)B_ * Q_ * N_ * F_;         // (B,Q,N,F)

    float *tmp, *h, *qkv, *S, *CP, *Wqkv;
    cudaGetSymbolAddress((void**)&tmp, g_tmp);
    cudaGetSymbolAddress((void**)&h, g_h);
    cudaGetSymbolAddress((void**)&qkv, g_qkv);
    cudaGetSymbolAddress((void**)&S, g_S);
    cudaGetSymbolAddress((void**)&CP, g_CP);
    cudaGetSymbolAddress((void**)&Wqkv, g_Wqkv);

    const long sNN = (long)N_ * N_;
    const long sNF = (long)N_ * F_;
    const long sQKV = (long)N_ * 3 * D_;
    const long sH = (long)N_ * D_;
    const int nBatch = B_ * Q_;            // 384

    // dynamic smem opt-in (capture-safe: attribute set only, no allocation)
    const int smNN = gemm_smem_bytes(128, 128, false);
    const int smNT = gemm_smem_bytes(128, 128, true);
    const int smN64 = gemm_smem_bytes(128, 64, false);
    cudaFuncSetAttribute(gemm_tc<128, 128, 2, 4, false, false, 0>,
                         cudaFuncAttributeMaxDynamicSharedMemorySize, smNN);
    cudaFuncSetAttribute(gemm_tc<128, 128, 2, 4, true, false, 0>,
                         cudaFuncAttributeMaxDynamicSharedMemorySize, smNT);
    cudaFuncSetAttribute(gemm_tc<128, 128, 2, 4, false, true, 0>,
                         cudaFuncAttributeMaxDynamicSharedMemorySize, smNN);
    cudaFuncSetAttribute(gemm_tc<128, 64, 2, 2, false, false, 0>,
                         cudaFuncAttributeMaxDynamicSharedMemorySize, smN64);
    cudaFuncSetAttribute(gemm_tc<128, 64, 2, 2, false, true, N_>,
                         cudaFuncAttributeMaxDynamicSharedMemorySize, smN64);

    // K1: time-mix
    mix_kernel<<<((long)B_ * N_ * F_ + 255) / 256, 256>>>(inputs, T_mix);

    // setup: Wqkv concat ; CP = [DT*A ; DT^2*A@A + 2DT*A]
    concat_w<<<(D_ * D_ + 255) / 256, 256>>>(Wq, Wk, Wv);
    scaleA_kernel<<<(N_ * N_ + 255) / 256, 256>>>(A);
    gemm_tc<128, 128, 2, 4, false, true, 0><<<dim3(4, 4, 1), 256, smNN>>>(
        A, A, CP + sNN, A, N_, N_, N_, N_, N_, N_, N_,
        0, 0, 0, 0, DT_ * DT_, 2.f * DT_);

    // K2: h = tmp @ W_in   (M=196608, N=256, K=64)
    gemm_tc<128, 128, 2, 4, false, false, 0><<<dim3(2, BQN / 128, 1), 256, smNN>>>(
        tmp, W_in, h, nullptr, BQN, D_, F_, F_, D_, D_, 0,
        0, 0, 0, 0, 1.f, 0.f);

    // K3: qkv = h @ Wqkv   (M=196608, N=768, K=256); q pre-scaled in Wqkv
    gemm_tc<128, 128, 2, 4, false, false, 0><<<dim3(6, BQN / 128, 1), 256, smNN>>>(
        h, Wqkv, qkv, nullptr, BQN, 3 * D_, D_, D_, 3 * D_, 3 * D_, 0,
        0, 0, 0, 0, 1.f, 0.f);

    // K4: S = q @ k^T   batched (512x512x256, NT); q at col 0, k at col 256
    gemm_tc<128, 128, 2, 4, true, false, 0><<<dim3(4, 4, nBatch), 256, smNT>>>(
        qkv, qkv + D_, S, nullptr, N_, N_, D_, 3 * D_, 3 * D_, N_, 0,
        sQKV, sQKV, sNN, 0, 1.f, 0.f);

    // K5: row softmax
    softmax_kernel<<<(BQN + 7) / 8, 256>>>();

    // K6: h = h + S @ v   batched (512x256x512, NN, residual); v at col 512
    gemm_tc<128, 128, 2, 4, false, true, 0><<<dim3(2, 4, nBatch), 256, smNN>>>(
        S, qkv + 2 * D_, h, h, N_, D_, N_, N_, 3 * D_, D_, D_,
        sNN, sQKV, sH, sH, 1.f, 1.f);

    // K7: mgt = h @ W_out   (M=196608, N=64, K=256)
    gemm_tc<128, 64, 2, 2, false, false, 0><<<dim3(1, BQN / 128, 1), 128, smN64>>>(
        h, W_out, mgt, nullptr, BQN, F_, D_, D_, F_, F_, 0,
        0, 0, 0, 0, 1.f, 0.f);

    // Kalman: [mu_{t+1}; mu_{t+2}] = CP @ mu_t + mu_t  (6 double-steps).
    for (int s = 0; s < Q_ / 2; s++) {
        const float* prev;
        long sB;
        if (s == 0) {
            prev = inputs + (long)(P_ - 1) * sNF;   // inputs[:, -1]
            sB = (long)P_ * sNF;
        } else {
            prev = kal + (long)(2 * s - 1) * sNF;
            sB = (long)Q_ * sNF;
        }
        gemm_tc<128, 64, 2, 2, false, true, N_><<<dim3(1, 8, B_), 128, smN64>>>(
            CP, prev, kal + (long)(2 * s) * sNF, prev,
            2 * N_, F_, N_, N_, F_, F_, F_,
            0, sB, (long)Q_ * sNF, sB, 1.f, 1.f);
    }
}

// round 6
// speedup vs baseline: 2.6845x; 1.1268x over previous
#include <cuda_runtime.h>
#include <cstdint>

// Problem dims
#define B_ 32
#define P_ 12
#define N_ 512
#define F_ 64
#define D_ 256
#define Q_ 12
#define DT_ 0.1f

static const int BQN = B_ * Q_ * N_;  // 196608

// ---------------- scratch (device globals; no runtime alloc) ----------------
__device__ float g_tmp  [(size_t)B_ * Q_ * N_ * F_];     // mixed inputs (tf32 bits)
__device__ float g_h    [(size_t)B_ * Q_ * N_ * D_];     // hidden (tf32 bits)
__device__ float g_qkv  [(size_t)B_ * Q_ * N_ * 3 * D_]; // q|k|v, ld=768 (tf32 bits)
__device__ float g_S    [(size_t)B_ * Q_ * N_ * N_];     // scores fp32 / attn tf32
__device__ float g_CP   [(size_t)2 * N_ * N_];           // [DT*A ; DT^2*A^2+2DT*A] tf32
__device__ float g_WinT [(size_t)D_ * F_];               // W_in^T  (256x64)  tf32
__device__ float g_WqkvT[(size_t)3 * D_ * D_];           // Wqkv^T  (768x256) tf32
__device__ float g_WoutT[(size_t)F_ * D_];               // W_out^T (64x256)  tf32

// ---------------- helpers ----------------------------------------------------
__device__ __forceinline__ uint32_t f2tf32(float f) {
    uint32_t u;
    asm("cvt.rna.tf32.f32 %0, %1;" : "=r"(u) : "f"(f));
    return u;
}
__device__ __forceinline__ float roundtf(float f) { return __uint_as_float(f2tf32(f)); }

__device__ __forceinline__ void mma_tf32(float* c, const uint32_t* a, const uint32_t* b) {
    asm volatile(
        "mma.sync.aligned.m16n8k8.row.col.f32.tf32.tf32.f32 "
        "{%0,%1,%2,%3}, {%4,%5,%6,%7}, {%8,%9}, {%0,%1,%2,%3};"
        : "+f"(c[0]), "+f"(c[1]), "+f"(c[2]), "+f"(c[3])
        : "r"(a[0]), "r"(a[1]), "r"(a[2]), "r"(a[3]),
          "r"(b[0]), "r"(b[1]));
}

__device__ __forceinline__ void ldsm_x4(uint32_t* r, uint32_t addr) {
    asm volatile("ldmatrix.sync.aligned.m8n8.x4.shared.b16 {%0,%1,%2,%3}, [%4];"
                 : "=r"(r[0]), "=r"(r[1]), "=r"(r[2]), "=r"(r[3]) : "r"(addr));
}

__device__ __forceinline__ void cp_async16(uint32_t smem_dst, const void* gsrc) {
    asm volatile("cp.async.cg.shared.global [%0], [%1], 16;\n" :: "r"(smem_dst), "l"(gsrc));
}

// ---------------- K1: tmp = time-mix(inputs), tf32-rounded -------------------
__global__ __launch_bounds__(256) void mix_kernel(const float* __restrict__ in,
                                                  const float* __restrict__ T) {
    __shared__ float Ts[P_][Q_];
    int t = threadIdx.x;
    if (t < P_ * Q_) Ts[t / Q_][t % Q_] = T[t];
    __syncthreads();
    long idx = (long)blockIdx.x * blockDim.x + t;          // over B*N*F
    if (idx >= (long)B_ * N_ * F_) return;
    int f = (int)(idx % F_);
    int n = (int)((idx / F_) % N_);
    int b = (int)(idx / ((long)F_ * N_));
    float vals[P_];
    const float* ip = in + ((long)b * P_ * N_ + n) * F_ + f;
#pragma unroll
    for (int p = 0; p < P_; p++) vals[p] = ip[(long)p * N_ * F_];
    float* op = g_tmp + ((long)b * Q_ * N_ + n) * F_ + f;
#pragma unroll
    for (int q = 0; q < Q_; q++) {
        float s = 0.f;
#pragma unroll
        for (int p = 0; p < P_; p++) s += vals[p] * Ts[p][q];
        op[(long)q * N_ * F_] = roundtf(s);
    }
}

// ---------------- setup: transposed + rounded weights, CP[0] -----------------
__global__ __launch_bounds__(256) void prep_weights(const float* __restrict__ Win,
                                                    const float* __restrict__ Wq,
                                                    const float* __restrict__ Wk,
                                                    const float* __restrict__ Wv,
                                                    const float* __restrict__ Wout) {
    int i = blockIdx.x * blockDim.x + threadIdx.x;
    if (i < D_ * D_) {            // Wq/Wk/Wv are DxD; transpose into WqkvT rows
        int r = i / D_, c = i % D_;
        g_WqkvT[(long)c * D_ + r]              = roundtf(Wq[i] * 0.0625f);
        g_WqkvT[(long)(D_ + c) * D_ + r]       = roundtf(Wk[i]);
        g_WqkvT[(long)(2 * D_ + c) * D_ + r]   = roundtf(Wv[i]);
    }
    if (i < F_ * D_) {            // W_in (F x D) -> WinT (D x F)
        int r = i / D_, c = i % D_;
        g_WinT[(long)c * F_ + r] = roundtf(Win[i]);
    }
    if (i < D_ * F_) {            // W_out (D x F) -> WoutT (F x D)
        int r = i / F_, c = i % F_;
        g_WoutT[(long)c * D_ + r] = roundtf(Wout[i]);
    }
}

__global__ __launch_bounds__(256) void scaleA_kernel(const float* __restrict__ A) {
    int i = blockIdx.x * blockDim.x + threadIdx.x;
    if (i < N_ * N_) g_CP[i] = roundtf(DT_ * A[i]);
}

// ---------------- tf32 tensor-core GEMM: cp.async x3 + ldmatrix --------------
// C = alpha * A * op(B) + beta * R (if RESID).  A: M x K (lda), row-major.
// NT: B is Nn x K (ldb), C = A*B^T. NN: B is K x Nn (ldb).
// CVT_A/CVT_B: operand needs tf32 rounding (else assumed pre-rounded bits).
// ROUND_C: store C tf32-rounded. RMOD>0: residual row = row % RMOD.
template <int BM, int BN, int WM, int WN, bool TRANS_B, bool RESID, int RMOD,
          bool CVT_A, bool CVT_B, bool ROUND_C>
__global__ __launch_bounds__(WM* WN * 32, 2) void gemm_tc(
    const float* __restrict__ A, const float* __restrict__ Bm,
    float* __restrict__ C, const float* __restrict__ R,
    int M, int Nn, int K, int lda, int ldb, int ldc, int ldr,
    long sA, long sB, long sC, long sR, float alpha, float beta) {
    constexpr int BK = 16;
    constexpr int STAGES = 3;
    constexpr int NTH = WM * WN * 32;
    constexpr int WTM = BM / WM;           // 64
    constexpr int WTN = BN / WN;           // 32
    constexpr int FM = WTM / 16;           // 4
    constexpr int FN = WTN / 8;            // 4
    constexpr int LDA_S = BK + 4;          // 20 words; ldmatrix rows conflict-free
    constexpr int LDB_S = BN + 8;
    constexpr int NA = BM * BK / (4 * NTH);
    constexpr int NB = BN * BK / (4 * NTH);
    constexpr int A_STAGE_B = BM * LDA_S * 4;
    constexpr int BT_STAGE_B = BN * LDA_S * 4;   // NT B stage bytes
    constexpr int BN_STAGE_B = BK * LDB_S * 4;   // NN B stage bytes

    extern __shared__ __align__(16) float smem[];
    float* As_ = smem;                                  // [STAGES][BM][LDA_S]
    float* Bs_ = smem + STAGES * BM * LDA_S;
    const uint32_t smem_u32 = (uint32_t)__cvta_generic_to_shared(smem);
    const uint32_t bs_u32 = smem_u32 + STAGES * A_STAGE_B;

    const int bz = blockIdx.z;
    A += (long)bz * sA;
    Bm += (long)bz * sB;
    C += (long)bz * sC;
    if (RESID) R += (long)bz * sR;

    const int row0 = blockIdx.y * BM, col0 = blockIdx.x * BN;
    const int tid = threadIdx.x;
    const int lane = tid & 31, wid = tid >> 5;
    const int grp = lane >> 2, qid = lane & 3;
    const int wm = wid / WN, wn = wid % WN;
    const int m_base = wm * WTM, n_base = wn * WTN;

    // ldmatrix per-lane base addresses (bytes)
    const int mi = lane >> 3, rr = lane & 7;
    const uint32_t aAddr0 = smem_u32 +
        (((m_base + ((mi & 1) << 3) + rr) * LDA_S + ((mi >> 1) << 2)) << 2);
    const uint32_t bAddr0 = bs_u32 +
        (((n_base + ((mi >> 1) << 3) + rr) * LDA_S + ((mi & 1) << 2)) << 2);

    float acc[FM][FN][4] = {};

    auto issue = [&](int st, int k0) {
#pragma unroll
        for (int l = 0; l < NA; l++) {
            int i = tid + l * NTH;
            int r = i >> 2, kq = i & 3;
            cp_async16(smem_u32 + st * A_STAGE_B + ((r * LDA_S + kq * 4) << 2),
                       A + (long)(row0 + r) * lda + k0 + kq * 4);
        }
#pragma unroll
        for (int l = 0; l < NB; l++) {
            int i = tid + l * NTH;
            if (!TRANS_B) {
                int kk = i / (BN / 4), nq = i % (BN / 4);
                cp_async16(bs_u32 + st * BN_STAGE_B + ((kk * LDB_S + nq * 4) << 2),
                           Bm + (long)(k0 + kk) * ldb + col0 + nq * 4);
            } else {
                int n = i >> 2, kq = i & 3;
                cp_async16(bs_u32 + st * BT_STAGE_B + ((n * LDA_S + kq * 4) << 2),
                           Bm + (long)(col0 + n) * ldb + k0 + kq * 4);
            }
        }
    };

    const int kt = K / BK;
#pragma unroll
    for (int s = 0; s < STAGES - 1; s++) {
        issue(s, s * BK);
        asm volatile("cp.async.commit_group;\n");
    }

    for (int t = 0; t < kt; t++) {
        asm volatile("cp.async.wait_group %0;\n" :: "n"(STAGES - 2));
        __syncthreads();
        const int st = t % STAGES;
        const int nx = t + STAGES - 1;
        if (nx < kt) issue(nx % STAGES, nx * BK);
        asm volatile("cp.async.commit_group;\n");

        const uint32_t aSt = aAddr0 + st * A_STAGE_B;
        const uint32_t bSt = bAddr0 + st * BT_STAGE_B;

#pragma unroll
        for (int kc = 0; kc < 2; kc++) {
            const int kk = kc * 8;
            uint32_t af[FM][4], bf[FN][2];
#pragma unroll
            for (int i = 0; i < FM; i++) {
                ldsm_x4(af[i], aSt + i * (16 * LDA_S * 4) + kc * 32);
                if (CVT_A) {
#pragma unroll
                    for (int q = 0; q < 4; q++) af[i][q] = f2tf32(__uint_as_float(af[i][q]));
                }
            }
            if (TRANS_B) {
#pragma unroll
                for (int jp = 0; jp < FN / 2; jp++) {
                    uint32_t tmp4[4];
                    ldsm_x4(tmp4, bSt + jp * (16 * LDA_S * 4) + kc * 32);
                    if (CVT_B) {
#pragma unroll
                        for (int q = 0; q < 4; q++) tmp4[q] = f2tf32(__uint_as_float(tmp4[q]));
                    }
                    bf[jp * 2][0] = tmp4[0]; bf[jp * 2][1] = tmp4[1];
                    bf[jp * 2 + 1][0] = tmp4[2]; bf[jp * 2 + 1][1] = tmp4[3];
                }
            } else {
#pragma unroll
                for (int j = 0; j < FN; j++) {
                    int n = n_base + j * 8 + grp;
                    float b0 = Bs_[(st * BK + kk + qid) * LDB_S + n];
                    float b1 = Bs_[(st * BK + kk + qid + 4) * LDB_S + n];
                    bf[j][0] = CVT_B ? f2tf32(b0) : __float_as_uint(b0);
                    bf[j][1] = CVT_B ? f2tf32(b1) : __float_as_uint(b1);
                }
            }
#pragma unroll
            for (int i = 0; i < FM; i++)
#pragma unroll
                for (int j = 0; j < FN; j++) mma_tf32(acc[i][j], af[i], bf[j]);
        }
    }

    // ---- epilogue ----
#pragma unroll
    for (int i = 0; i < FM; i++) {
        int r0 = row0 + m_base + i * 16 + grp;
#pragma unroll
        for (int j = 0; j < FN; j++) {
            int c = col0 + n_base + j * 8 + qid * 2;
            float2 v0 = {acc[i][j][0] * alpha, acc[i][j][1] * alpha};
            float2 v1 = {acc[i][j][2] * alpha, acc[i][j][3] * alpha};
            if (RESID) {
                int rr0 = RMOD ? (r0 % RMOD) : r0;
                int rr1 = RMOD ? ((r0 + 8) % RMOD) : (r0 + 8);
                float2 r0v = *(const float2*)(R + (long)rr0 * ldr + c);
                float2 r1v = *(const float2*)(R + (long)rr1 * ldr + c);
                v0.x += beta * r0v.x; v0.y += beta * r0v.y;
                v1.x += beta * r1v.x; v1.y += beta * r1v.y;
            }
            if (ROUND_C) {
                v0.x = roundtf(v0.x); v0.y = roundtf(v0.y);
                v1.x = roundtf(v1.x); v1.y = roundtf(v1.y);
            }
            *(float2*)(C + (long)r0 * ldc + c) = v0;
            *(float2*)(C + (long)(r0 + 8) * ldc + c) = v1;
        }
    }
}

// host-side smem size mirror
static inline int gemm_smem_bytes(int BM, int BN, bool transB) {
    const int STAGES = 3, BK = 16, LDA_S = 20;
    int a = STAGES * BM * LDA_S;
    int b = transB ? STAGES * BN * LDA_S : STAGES * BK * (BN + 8);
    return (a + b) * 4;
}

// ---------------- row softmax over 512, output tf32-rounded -----------------
__global__ __launch_bounds__(256) void softmax_kernel() {
    long row = (long)blockIdx.x * 8 + (threadIdx.x >> 5);
    int lane = threadIdx.x & 31;
    if (row >= (long)B_ * Q_ * N_) return;
    float* p = g_S + row * N_;
    float vals[16];
    float m = -1e30f;
#pragma unroll
    for (int i = 0; i < 16; i++) {
        vals[i] = p[lane + i * 32];
        m = fmaxf(m, vals[i]);
    }
#pragma unroll
    for (int o = 16; o; o >>= 1) m = fmaxf(m, __shfl_xor_sync(0xffffffffu, m, o));
    float s = 0.f;
#pragma unroll
    for (int i = 0; i < 16; i++) {
        vals[i] = __expf(vals[i] - m);
        s += vals[i];
    }
#pragma unroll
    for (int o = 16; o; o >>= 1) s += __shfl_xor_sync(0xffffffffu, s, o);
    float inv = 1.f / s;
#pragma unroll
    for (int i = 0; i < 16; i++) p[lane + i * 32] = roundtf(vals[i] * inv);
}

// ---------------- launch ----------------------------------------------------
extern "C" void kernel_launch(void* const* d_in, const int* in_sizes, int n_in,
                              void* d_out, int out_size) {
    const float* inputs = (const float*)d_in[0];
    const float* W_in  = (const float*)d_in[2];
    const float* T_mix = (const float*)d_in[3];
    const float* Wq    = (const float*)d_in[4];
    const float* Wk    = (const float*)d_in[5];
    const float* Wv    = (const float*)d_in[6];
    const float* W_out = (const float*)d_in[7];
    const float* A     = (const float*)d_in[8];

    float* out = (float*)d_out;
    float* mgt = out;
    float* kal = out + (long)B_ * Q_ * N_ * F_;

    float *tmp, *h, *qkv, *S, *CP, *WinT, *WqkvT, *WoutT;
    cudaGetSymbolAddress((void**)&tmp, g_tmp);
    cudaGetSymbolAddress((void**)&h, g_h);
    cudaGetSymbolAddress((void**)&qkv, g_qkv);
    cudaGetSymbolAddress((void**)&S, g_S);
    cudaGetSymbolAddress((void**)&CP, g_CP);
    cudaGetSymbolAddress((void**)&WinT, g_WinT);
    cudaGetSymbolAddress((void**)&WqkvT, g_WqkvT);
    cudaGetSymbolAddress((void**)&WoutT, g_WoutT);

    const long sNN = (long)N_ * N_;
    const long sNF = (long)N_ * F_;
    const long sQKV = (long)N_ * 3 * D_;
    const long sH = (long)N_ * D_;
    const int nBatch = B_ * Q_;            // 384

    // GEMM instances
    auto kNT   = gemm_tc<128, 128, 2, 4, true,  false, 0,  false, false, true>;   // K2, K3
    auto kNT_S = gemm_tc<128, 128, 2, 4, true,  false, 0,  false, false, false>;  // K4
    auto kNN_R = gemm_tc<128, 128, 2, 4, false, true,  0,  false, false, true>;   // K6
    auto kOUT  = gemm_tc<128, 64,  2, 2, true,  false, 0,  false, false, false>;  // K7
    auto kKAL  = gemm_tc<128, 64,  2, 2, false, true,  N_, false, true,  false>;  // Kalman
    auto kCP   = gemm_tc<128, 128, 2, 4, false, true,  0,  true,  true,  true>;   // CP setup

    const int smNT   = gemm_smem_bytes(128, 128, true);
    const int smNN   = gemm_smem_bytes(128, 128, false);
    const int smNT64 = gemm_smem_bytes(128, 64, true);
    const int smNN64 = gemm_smem_bytes(128, 64, false);
    cudaFuncSetAttribute(kNT,   cudaFuncAttributeMaxDynamicSharedMemorySize, smNT);
    cudaFuncSetAttribute(kNT_S, cudaFuncAttributeMaxDynamicSharedMemorySize, smNT);
    cudaFuncSetAttribute(kNN_R, cudaFuncAttributeMaxDynamicSharedMemorySize, smNN);
    cudaFuncSetAttribute(kOUT,  cudaFuncAttributeMaxDynamicSharedMemorySize, smNT64);
    cudaFuncSetAttribute(kKAL,  cudaFuncAttributeMaxDynamicSharedMemorySize, smNN64);
    cudaFuncSetAttribute(kCP,   cudaFuncAttributeMaxDynamicSharedMemorySize, smNN);

    // K1 + setup
    mix_kernel<<<((long)B_ * N_ * F_ + 255) / 256, 256>>>(inputs, T_mix);
    prep_weights<<<(D_ * D_ + 255) / 256, 256>>>(W_in, Wq, Wk, Wv, W_out);
    scaleA_kernel<<<(N_ * N_ + 255) / 256, 256>>>(A);
    // CP[1] = DT^2*A@A + 2DT*A (NN, cvt both operands, residual raw A)
    kCP<<<dim3(4, 4, 1), 256, smNN>>>(
        A, A, CP + sNN, A, N_, N_, N_, N_, N_, N_, N_,
        0, 0, 0, 0, DT_ * DT_, 2.f * DT_);

    // K2: h = tmp @ WinT^T   (NT: B = WinT [256x64])
    kNT<<<dim3(2, BQN / 128, 1), 256, smNT>>>(
        tmp, WinT, h, nullptr, BQN, D_, F_, F_, F_, D_, 0,
        0, 0, 0, 0, 1.f, 0.f);

    // K3: qkv = h @ WqkvT^T  (NT: B = WqkvT [768x256])
    kNT<<<dim3(6, BQN / 128, 1), 256, smNT>>>(
        h, WqkvT, qkv, nullptr, BQN, 3 * D_, D_, D_, D_, 3 * D_, 0,
        0, 0, 0, 0, 1.f, 0.f);

    // K4: S = q @ k^T  batched (NT)
    kNT_S<<<dim3(4, 4, nBatch), 256, smNT>>>(
        qkv, qkv + D_, S, nullptr, N_, N_, D_, 3 * D_, 3 * D_, N_, 0,
        sQKV, sQKV, sNN, 0, 1.f, 0.f);

    // K5: softmax (rounds attn to tf32)
    softmax_kernel<<<(BQN + 7) / 8, 256>>>();

    // K6: h = h + attn @ v  batched (NN, residual)
    kNN_R<<<dim3(2, 4, nBatch), 256, smNN>>>(
        S, qkv + 2 * D_, h, h, N_, D_, N_, N_, 3 * D_, D_, D_,
        sNN, sQKV, sH, sH, 1.f, 1.f);

    // K7: mgt = h @ WoutT^T  (NT: B = WoutT [64x256])
    kOUT<<<dim3(1, BQN / 128, 1), 128, smNT64>>>(
        h, WoutT, mgt, nullptr, BQN, F_, D_, D_, D_, F_, 0,
        0, 0, 0, 0, 1.f, 0.f);

    // Kalman: [mu_{t+1}; mu_{t+2}] = CP @ mu_t + mu_t  (6 double-steps)
    for (int s = 0; s < Q_ / 2; s++) {
        const float* prev;
        long sB;
        if (s == 0) {
            prev = inputs + (long)(P_ - 1) * sNF;
            sB = (long)P_ * sNF;
        } else {
            prev = kal + (long)(2 * s - 1) * sNF;
            sB = (long)Q_ * sNF;
        }
        kKAL<<<dim3(1, 8, B_), 128, smNN64>>>(
            CP, prev, kal + (long)(2 * s) * sNF, prev,
            2 * N_, F_, N_, N_, F_, F_, F_,
            0, sB, (long)Q_ * sNF, sB, 1.f, 1.f);
    }
}